// round 16
// baseline (speedup 1.0000x reference)
#include <cuda_runtime.h>
#include <cuda_bf16.h>
#include <math.h>
#include <stdint.h>

#define BB 64
#define TT 1024
#define FF 128
#define UU 256

typedef unsigned long long ull;

// Per-batch progress counters (chunks of 32 t-rows published by proj CTAs).
// Zero at module load; reset_kernel re-zeroes after every run so graph
// replays are deterministic.
__device__ int progress_g[BB];

// ---------------------------------------------------------------------------
// Packed f32x2 helpers (sm_100+): two independent fp32 FMAs per instruction,
// exact fp32 arithmetic.
// ---------------------------------------------------------------------------
__device__ __forceinline__ void ffma2(ull &d, ull a, ull b) {
    asm("fma.rn.f32x2 %0, %1, %2, %0;" : "+l"(d) : "l"(a), "l"(b));
}
__device__ __forceinline__ ull packf2(float lo, float hi) {
    ull r;
    asm("mov.b64 %0, {%1, %2};" : "=l"(r) : "f"(lo), "f"(hi));
    return r;
}
__device__ __forceinline__ float f2lo(ull v) { return __uint_as_float((unsigned)v); }
__device__ __forceinline__ float f2hi(ull v) { return __uint_as_float((unsigned)(v >> 32)); }

// Fast tanh via MUFU.EX2 + MUFU.RCP (rel err ~1e-6 on this recurrence's range).
__device__ __forceinline__ float tanh_fast(float y) {
    float e = __expf(2.0f * y);
    return 1.0f - __fdividef(2.0f, e + 1.0f);
}

// Acquire load for the progress poll (pairs with producer fence+atomic).
__device__ __forceinline__ int ld_acquire(const int* p) {
    int v;
    asm volatile("ld.acquire.gpu.global.s32 %0, [%1];" : "=r"(v) : "l"(p));
    return v;
}

// Named block barriers (512 participants) for the rec finalize split.
__device__ __forceinline__ void bar_sync1()   { asm volatile("bar.sync 1, 512;"   ::: "memory"); }
__device__ __forceinline__ void bar_arrive1() { asm volatile("bar.arrive 1, 512;" ::: "memory"); }
__device__ __forceinline__ void bar_sync2()   { asm volatile("bar.sync 2, 512;"   ::: "memory"); }

// ---------------------------------------------------------------------------
// Fused kernel, grid = 128 CTAs x 512 threads, all co-resident (1 CTA/SM):
//   CTA b in [0,64):    recurrence for batch b (consumes h from d_out)
//   CTA 64+b:           projection h[t,b,u] = inputs[b,t,:]@R + bias into
//                       d_out, publishing progress_g[b] per 32-row chunk.
// rec gates on progress with an acquire load; proj releases with
// threadfence + syncthreads + atomicAdd.
// ---------------------------------------------------------------------------
#define FUSED_SMEM (128 * 1024 + 32 * 128 * 4)   /* proj role: 144 KB (max) */

__global__ __launch_bounds__(512, 1)
void fused_kernel(const float* __restrict__ inp, const float* __restrict__ R,
                  const float* __restrict__ W,   const float* __restrict__ bias,
                  const float* __restrict__ x0,  float* __restrict__ out)
{
    extern __shared__ ull smem[];
    const int tid = threadIdx.x;

    if (blockIdx.x >= 64) {
        // =================== PROJECTION ROLE ===================
        const int b = blockIdx.x - 64;
        ull*   Rs  = smem;                    // 16384 ull: Rs[p*256+u] = (R[2p][u], R[2p+1][u])
        float* xin = (float*)(smem + 16384);  // 32 rows x 128 floats

        // Fill Rs once (coalesced over u).
        #pragma unroll 1
        for (int i = 0; i < 32; ++i) {
            int e = i * 512 + tid;
            int u = e & 255, p = e >> 8;
            Rs[p * 256 + u] = packf2(R[(2 * p) * UU + u], R[(2 * p + 1) * UU + u]);
        }

        const float4* src = (const float4*)(inp + (size_t)b * TT * FF);
        float4 pf0 = src[tid], pf1 = src[512 + tid];

        const int uu = tid & 63;
        const int rg = tid >> 6;              // 0..7, rows rg*4..rg*4+3
        const int u0 = uu * 4;
        const ulonglong2* Rs2 = (const ulonglong2*)Rs;
        const ulonglong2* xr2 = (const ulonglong2*)xin;

        const float4 bb = *(const float4*)(bias + u0);

        #pragma unroll 1
        for (int ch = 0; ch < 32; ++ch) {
            float4* dst = (float4*)xin;
            dst[tid] = pf0; dst[512 + tid] = pf1;
            __syncthreads();

            int chn = (ch + 1 < 32) ? ch + 1 : ch;
            pf0 = src[chn * 1024 + tid];
            pf1 = src[chn * 1024 + 512 + tid];

            ull acc[16];
            #pragma unroll
            for (int i = 0; i < 16; ++i) acc[i] = 0ull;

            #pragma unroll 2
            for (int pp = 0; pp < 32; ++pp) {
                int p0 = 2 * pp, p1 = 2 * pp + 1;
                ulonglong2 wA01 = Rs2[(p0 * 256 + u0) >> 1];
                ulonglong2 wA23 = Rs2[((p0 * 256 + u0) >> 1) + 1];
                ulonglong2 wB01 = Rs2[(p1 * 256 + u0) >> 1];
                ulonglong2 wB23 = Rs2[((p1 * 256 + u0) >> 1) + 1];
                #pragma unroll
                for (int ri = 0; ri < 4; ++ri) {
                    ulonglong2 xv = xr2[(rg * 4 + ri) * 32 + pp];  // broadcast LDS.128
                    ffma2(acc[ri * 4 + 0], xv.x, wA01.x);
                    ffma2(acc[ri * 4 + 1], xv.x, wA01.y);
                    ffma2(acc[ri * 4 + 2], xv.x, wA23.x);
                    ffma2(acc[ri * 4 + 3], xv.x, wA23.y);
                    ffma2(acc[ri * 4 + 0], xv.y, wB01.x);
                    ffma2(acc[ri * 4 + 1], xv.y, wB01.y);
                    ffma2(acc[ri * 4 + 2], xv.y, wB23.x);
                    ffma2(acc[ri * 4 + 3], xv.y, wB23.y);
                }
            }

            #pragma unroll
            for (int ri = 0; ri < 4; ++ri) {
                int t = ch * 32 + rg * 4 + ri;
                float4 v;
                v.x = f2lo(acc[ri * 4 + 0]) + f2hi(acc[ri * 4 + 0]) + bb.x;
                v.y = f2lo(acc[ri * 4 + 1]) + f2hi(acc[ri * 4 + 1]) + bb.y;
                v.z = f2lo(acc[ri * 4 + 2]) + f2hi(acc[ri * 4 + 2]) + bb.z;
                v.w = f2lo(acc[ri * 4 + 3]) + f2hi(acc[ri * 4 + 3]) + bb.w;
                *(float4*)(out + (size_t)t * (BB * UU) + (size_t)b * UU + u0) = v;
            }

            // Publish chunk ch: release pattern (fence by all, bar, one atomic).
            __threadfence();
            __syncthreads();
            if (tid == 0) atomicAdd(&progress_g[b], 1);
        }
        return;
    }

    // =================== RECURRENCE ROLE ===================
    // Smem-W pairs re-mapped to {3,7,11,15} (one per ODD chunk) so the 8
    // Wsm LDS.128 spread evenly across the FMA loop instead of piling into
    // the tail: crossbar and FMA-issue overlap (max instead of sum).
    const int b = blockIdx.x;
    ulonglong2* Wsm2    = (ulonglong2*)smem;           // 8 slots * 512 ull2 = 64 KB
    float*      sxf     = (float*)(smem + 8192);       // 256 floats (state)
    float*      partial = sxf + 256;                   // 8 * 256 floats

    const int kq  = tid >> 6;        // 0..7
    const int u0  = (tid & 63) * 4;
    const int k0  = kq * 32;

    // --- Load W partition: local pairs p=0..15; {3,7,11,15} -> smem slots
    //     q=(p-3)/4, rest -> wreg in consumption order (see step loop) ---
    ull wreg[4][12];
    #pragma unroll
    for (int p = 0; p < 16; ++p) {
        float4 va = *(const float4*)(W + (size_t)(k0 + 2 * p)     * UU + u0);
        float4 vb = *(const float4*)(W + (size_t)(k0 + 2 * p + 1) * UU + u0);
        ull w0 = packf2(va.x, vb.x);
        ull w1 = packf2(va.y, vb.y);
        ull w2 = packf2(va.z, vb.z);
        ull w3 = packf2(va.w, vb.w);
        if ((p & 3) == 3) {
            int q = (p - 3) >> 2;                      // 0..3
            Wsm2[(q * 2 + 0) * 512 + tid] = make_ulonglong2(w0, w1);
            Wsm2[(q * 2 + 1) * 512 + tid] = make_ulonglong2(w2, w3);
        } else {
            // reg index: consumption order = p minus #smem pairs below p
            int idx = p - ((p > 3) ? 1 : 0) - ((p > 7) ? 1 : 0) - ((p > 11) ? 1 : 0);
            wreg[0][idx] = w0; wreg[1][idx] = w1; wreg[2][idx] = w2; wreg[3][idx] = w3;
        }
    }

    if (tid < 256) sxf[tid] = x0[tid];
    __syncthreads();

    float* outp = out + (size_t)b * UU + tid;                 // deref only tid<256
    const ulonglong2* sx2 = (const ulonglong2*)sxf + kq * 8;  // this kq's 16 pairs

    float hcur = 0.f;                                         // h[t], depth-2 pipeline

    #pragma unroll 1
    for (int t = 0; t < TT; ++t) {
        // Gate one chunk AHEAD (covers the h[t+1] prefetch below).
        if ((t & 31) == 0) {
            int need = (t >> 5) + 2;
            if (need > 32) need = 32;
            while (ld_acquire(&progress_g[b]) < need) { }
        }
        // Depth-2 h prefetch: issue h[t+1] now, consume at step t+1 finalize.
        int tn = (t + 1 < TT) ? t + 1 : t;
        float hnext = 0.f;
        if (tid < 256) {
            hnext = outp[(size_t)tn * (BB * UU)];
            if (t == 0) hcur = outp[0];
        }

        ull a0 = 0, a1 = 0, a2 = 0, a3 = 0;
        ulonglong2 sp;

        // rolling smem-W window: wp = pair for next odd chunk
        ulonglong2 wp0 = Wsm2[0 * 512 + tid];   // pair 3 (chunk 1)
        ulonglong2 wp1 = Wsm2[1 * 512 + tid];

        // chunk 0: pairs 0,1 (reg idx 0,1)
        sp = sx2[0];
        ffma2(a0, sp.x, wreg[0][0]); ffma2(a1, sp.x, wreg[1][0]);
        ffma2(a2, sp.x, wreg[2][0]); ffma2(a3, sp.x, wreg[3][0]);
        ffma2(a0, sp.y, wreg[0][1]); ffma2(a1, sp.y, wreg[1][1]);
        ffma2(a2, sp.y, wreg[2][1]); ffma2(a3, sp.y, wreg[3][1]);
        // chunk 1: pair 2 (reg idx 2) + pair 3 (smem wp); prefetch pair 7
        sp = sx2[1];
        {
            ulonglong2 wn0 = Wsm2[2 * 512 + tid];
            ulonglong2 wn1 = Wsm2[3 * 512 + tid];
            ffma2(a0, sp.x, wreg[0][2]); ffma2(a1, sp.x, wreg[1][2]);
            ffma2(a2, sp.x, wreg[2][2]); ffma2(a3, sp.x, wreg[3][2]);
            ffma2(a0, sp.y, wp0.x); ffma2(a1, sp.y, wp0.y);
            ffma2(a2, sp.y, wp1.x); ffma2(a3, sp.y, wp1.y);
            wp0 = wn0; wp1 = wn1;
        }
        // chunk 2: pairs 4,5 (reg idx 3,4)
        sp = sx2[2];
        ffma2(a0, sp.x, wreg[0][3]); ffma2(a1, sp.x, wreg[1][3]);
        ffma2(a2, sp.x, wreg[2][3]); ffma2(a3, sp.x, wreg[3][3]);
        ffma2(a0, sp.y, wreg[0][4]); ffma2(a1, sp.y, wreg[1][4]);
        ffma2(a2, sp.y, wreg[2][4]); ffma2(a3, sp.y, wreg[3][4]);
        // chunk 3: pair 6 (reg idx 5) + pair 7 (smem wp); prefetch pair 11
        sp = sx2[3];
        {
            ulonglong2 wn0 = Wsm2[4 * 512 + tid];
            ulonglong2 wn1 = Wsm2[5 * 512 + tid];
            ffma2(a0, sp.x, wreg[0][5]); ffma2(a1, sp.x, wreg[1][5]);
            ffma2(a2, sp.x, wreg[2][5]); ffma2(a3, sp.x, wreg[3][5]);
            ffma2(a0, sp.y, wp0.x); ffma2(a1, sp.y, wp0.y);
            ffma2(a2, sp.y, wp1.x); ffma2(a3, sp.y, wp1.y);
            wp0 = wn0; wp1 = wn1;
        }
        // chunk 4: pairs 8,9 (reg idx 6,7)
        sp = sx2[4];
        ffma2(a0, sp.x, wreg[0][6]); ffma2(a1, sp.x, wreg[1][6]);
        ffma2(a2, sp.x, wreg[2][6]); ffma2(a3, sp.x, wreg[3][6]);
        ffma2(a0, sp.y, wreg[0][7]); ffma2(a1, sp.y, wreg[1][7]);
        ffma2(a2, sp.y, wreg[2][7]); ffma2(a3, sp.y, wreg[3][7]);
        // chunk 5: pair 10 (reg idx 8) + pair 11 (smem wp); prefetch pair 15
        sp = sx2[5];
        {
            ulonglong2 wn0 = Wsm2[6 * 512 + tid];
            ulonglong2 wn1 = Wsm2[7 * 512 + tid];
            ffma2(a0, sp.x, wreg[0][8]); ffma2(a1, sp.x, wreg[1][8]);
            ffma2(a2, sp.x, wreg[2][8]); ffma2(a3, sp.x, wreg[3][8]);
            ffma2(a0, sp.y, wp0.x); ffma2(a1, sp.y, wp0.y);
            ffma2(a2, sp.y, wp1.x); ffma2(a3, sp.y, wp1.y);
            wp0 = wn0; wp1 = wn1;
        }
        // chunk 6: pairs 12,13 (reg idx 9,10)
        sp = sx2[6];
        ffma2(a0, sp.x, wreg[0][9]);  ffma2(a1, sp.x, wreg[1][9]);
        ffma2(a2, sp.x, wreg[2][9]);  ffma2(a3, sp.x, wreg[3][9]);
        ffma2(a0, sp.y, wreg[0][10]); ffma2(a1, sp.y, wreg[1][10]);
        ffma2(a2, sp.y, wreg[2][10]); ffma2(a3, sp.y, wreg[3][10]);
        // chunk 7: pair 14 (reg idx 11) + pair 15 (smem wp)
        sp = sx2[7];
        ffma2(a0, sp.x, wreg[0][11]); ffma2(a1, sp.x, wreg[1][11]);
        ffma2(a2, sp.x, wreg[2][11]); ffma2(a3, sp.x, wreg[3][11]);
        ffma2(a0, sp.y, wp0.x); ffma2(a1, sp.y, wp0.y);
        ffma2(a2, sp.y, wp1.x); ffma2(a3, sp.y, wp1.y);

        float4 ps;
        ps.x = f2lo(a0) + f2hi(a0);
        ps.y = f2lo(a1) + f2hi(a1);
        ps.z = f2lo(a2) + f2hi(a2);
        ps.w = f2lo(a3) + f2hi(a3);
        *(float4*)(partial + kq * 256 + u0) = ps;             // STS.128 conflict-free

        if (tid < 256) {
            bar_sync1();                                      // wait for all partials
            float s0 = partial[           tid] + partial[ 256 + tid];
            float s1 = partial[ 512 + tid] + partial[ 768 + tid];
            float s2 = partial[1024 + tid] + partial[1280 + tid];
            float s3 = partial[1536 + tid] + partial[1792 + tid];
            float y  = ((s0 + s1) + (s2 + s3)) + hcur;
            float x  = tanh_fast(y);
            sxf[tid] = x;                                     // new state
            outp[(size_t)t * (BB * UU)] = x;                  // overwrite h[t]
            bar_sync2();                                      // state visible to all
        } else {
            bar_arrive1();                                    // non-blocking
            bar_sync2();                                      // single wait per step
        }
        hcur = hnext;
    }
}

// Reset progress counters so every run (and every graph replay) starts at 0.
__global__ void reset_kernel() {
    if (threadIdx.x < BB) progress_g[threadIdx.x] = 0;
}

// ---------------------------------------------------------------------------
// Launch. Inputs: inputs[B,T,F], R[F,U], W[U,U], bias[U], x0[U].
// Output: float32 states[T,B,U]. One fused 128-CTA kernel + tiny reset.
// ---------------------------------------------------------------------------
extern "C" void kernel_launch(void* const* d_in, const int* in_sizes, int n_in,
                              void* d_out, int out_size) {
    const float* inp  = (const float*)d_in[0];
    const float* R    = (const float*)d_in[1];
    const float* W    = (const float*)d_in[2];
    const float* bias = (const float*)d_in[3];
    const float* x0   = (const float*)d_in[4];
    float* out = (float*)d_out;

    cudaFuncSetAttribute(fused_kernel, cudaFuncAttributeMaxDynamicSharedMemorySize, FUSED_SMEM);

    fused_kernel<<<2 * BB, 512, FUSED_SMEM>>>(inp, R, W, bias, x0, out);
    reset_kernel<<<1, 64>>>();
}